// round 16
// baseline (speedup 1.0000x reference)
#include <cuda_runtime.h>
#include <math.h>

#define KDT   0.1f
#define KG    9.81f
#define KRHO  1028.0f

typedef unsigned long long u64;

// Duplicated-constant layout: every scalar stored TWICE consecutively so a
// 64-bit constant-bank operand yields (c, c) for lane-paired f32x2 math.
// Matrices column-major by t = j*6+i; element pair at base + 2*t.
// [0:72)    Minv        [72:144)  mTot      [144:216) MiLD = Minv@linDamp
// [216:288) linDampFow  [288:300) quadDamp diag
// [300:336) negGm (6x3, t = jj*6+i)
// [336]     lf-nonzero flag
#define CMINV  0
#define CMTOT  72
#define CMILD  144
#define CLF    216
#define CQD    288
#define CNEGGM 300
#define CFLAG  336
#define NC     344
__constant__ __align__(16) float c_consts[NC];

// Parallel prep (64 threads): Gauss-Jordan in shared, duplicated stores
// directly into the constant-bank backing store (launch boundary flushes
// constant caches before the main kernel reads).
__global__ void prep_kernel(float* __restrict__ c_dst,
                            const float* mass, const float* volume,
                            const float* cog, const float* cob,
                            const float* mTot, const float* linDamp,
                            const float* linDampFow, const float* quadDamp) {
    __shared__ float As[36], Bs[36], MiLD[36], Ag[18], fv[6];
    __shared__ int piv_s;

    const int t = threadIdx.x;
    const int r = t / 6, c = t % 6;

    if (t < 36) { As[t] = mTot[t]; Bs[t] = (r == c) ? 1.0f : 0.0f; }
    __syncthreads();

    for (int k = 0; k < 6; k++) {
        if (t == 0) {
            int piv = k; float best = fabsf(As[k * 6 + k]);
            for (int rr = k + 1; rr < 6; rr++) {
                float a = fabsf(As[rr * 6 + k]);
                if (a > best) { best = a; piv = rr; }
            }
            piv_s = piv;
        }
        __syncthreads();
        const int piv = piv_s;
        if (piv != k && t < 6) {
            float tmp = As[k * 6 + t]; As[k * 6 + t] = As[piv * 6 + t]; As[piv * 6 + t] = tmp;
            tmp = Bs[k * 6 + t]; Bs[k * 6 + t] = Bs[piv * 6 + t]; Bs[piv * 6 + t] = tmp;
        }
        __syncthreads();
        const float inv = 1.0f / As[k * 6 + k];
        if (t < 6) { As[k * 6 + t] *= inv; Bs[k * 6 + t] *= inv; }
        __syncthreads();
        if (t < 6) fv[t] = As[t * 6 + k];
        __syncthreads();
        if (t < 36 && r != k) {
            const float f = fv[r];
            As[t] -= f * As[k * 6 + c];
            Bs[t] -= f * Bs[k * 6 + c];
        }
        __syncthreads();
    }
    // Bs = Minv (row-major)

    if (t < 36) {
        float acc = 0.0f;
        for (int kk = 0; kk < 6; kk++) acc += Bs[r * 6 + kk] * linDamp[kk * 6 + c];
        MiLD[t] = acc;   // MiLD row-major: MiLD[r*6+c]
    }

    if (t == 0) {
        const float fgz = -mass[0] * KG;
        const float fbz = volume[0] * KRHO * KG;
        for (int ii = 0; ii < 18; ii++) Ag[ii] = 0.0f;
        Ag[0 * 3 + 0] = Ag[1 * 3 + 1] = Ag[2 * 3 + 2] = -(fgz + fbz);
        const float cg0 = cog[0], cg1 = cog[1], cg2 = cog[2];
        const float cb0 = cob[0], cb1 = cob[1], cb2 = cob[2];
        Ag[3 * 3 + 1] = -(-fgz * cg2 - fbz * cb2);
        Ag[3 * 3 + 2] = -( fgz * cg1 + fbz * cb1);
        Ag[4 * 3 + 0] = -( fgz * cg2 + fbz * cb2);
        Ag[4 * 3 + 2] = -(-fgz * cg0 - fbz * cb0);
        Ag[5 * 3 + 0] = -(-fgz * cg1 - fbz * cb1);
        Ag[5 * 3 + 1] = -( fgz * cg0 + fbz * cb0);
    }
    __syncthreads();

    // Duplicated column-major stores: t = j*6+i -> i = t%6, j = t/6
    if (t < 36) {
        const int i = t % 6, j = t / 6;
        const float mi = Bs[i * 6 + j];
        const float mt = mTot[i * 6 + j];
        const float ml = MiLD[i * 6 + j];
        const float lf = linDampFow[i * 6 + j];
        c_dst[CMINV + 2 * t] = mi;  c_dst[CMINV + 2 * t + 1] = mi;
        c_dst[CMTOT + 2 * t] = mt;  c_dst[CMTOT + 2 * t + 1] = mt;
        c_dst[CMILD + 2 * t] = ml;  c_dst[CMILD + 2 * t + 1] = ml;
        c_dst[CLF   + 2 * t] = lf;  c_dst[CLF   + 2 * t + 1] = lf;
    }
    if (t < 6) {
        const float qd = quadDamp[t * 7];
        c_dst[CQD + 2 * t] = qd;  c_dst[CQD + 2 * t + 1] = qd;
    }
    if (t < 18) {
        const int i = t % 6, jj = t / 6;
        float acc = 0.0f;
        for (int kk = 0; kk < 6; kk++) acc += Bs[i * 6 + kk] * Ag[kk * 3 + jj];
        c_dst[CNEGGM + 2 * t] = -acc;  c_dst[CNEGGM + 2 * t + 1] = -acc;
    }
    if (t == 32) {
        float nz = 0.0f;
        for (int ii = 0; ii < 36; ii++)
            if (linDampFow[ii] != 0.0f) nz = 1.0f;
        c_dst[CFLAG] = nz;
    }
}

// ---------------- packed f32x2 helpers (lanes = two rows) ----------------
__device__ __forceinline__ u64 pk2(float lo, float hi) {
    u64 r; asm("mov.b64 %0,{%1,%2};" : "=l"(r) : "f"(lo), "f"(hi)); return r;
}
__device__ __forceinline__ u64 splat2(float a) {
    u64 r; asm("mov.b64 %0,{%1,%1};" : "=l"(r) : "f"(a)); return r;
}
__device__ __forceinline__ void unpk2(u64 p, float& lo, float& hi) {
    asm("mov.b64 {%0,%1},%2;" : "=f"(lo), "=f"(hi) : "l"(p));
}
__device__ __forceinline__ u64 f2fma(u64 a, u64 b, u64 c) {
    u64 d; asm("fma.rn.f32x2 %0,%1,%2,%3;" : "=l"(d) : "l"(a), "l"(b), "l"(c)); return d;
}
__device__ __forceinline__ u64 f2mul(u64 a, u64 b) {
    u64 d; asm("mul.rn.f32x2 %0,%1,%2;" : "=l"(d) : "l"(a), "l"(b)); return d;
}
__device__ __forceinline__ u64 f2add(u64 a, u64 b) {
    u64 d; asm("add.rn.f32x2 %0,%1,%2;" : "=l"(d) : "l"(a), "l"(b)); return d;
}
__device__ __forceinline__ u64 f2abs(u64 a) { return a & 0x7FFFFFFF7FFFFFFFULL; }

// Duplicated-constant 64-bit fetch: (c, c) directly as FFMA2 operand.
#define CD(base, t) (*reinterpret_cast<const u64*>(&c_consts[(base) + 2 * (t)]))

// One RK stage, lane-paired (each u64 = same quantity for rows A and B).
// sub(a,b) = a - b implemented as fma(b, -1, a) via the n1 splat.
__device__ __forceinline__ void stage_pair(const u64 q[4], const u64 v[6],
                                           const u64 Uv[6],
                                           u64 pd[7], u64 vd[6]) {
    const u64 one  = splat2(1.0f);
    const u64 two  = splat2(2.0f);
    const u64 n2   = splat2(-2.0f);
    const u64 half = splat2(0.5f);
    const u64 nhalf= splat2(-0.5f);
    const u64 n1   = splat2(-1.0f);
#define SUBP(a, b) f2fma((b), n1, (a))

    const u64 qx = q[0], qy = q[1], qz = q[2], qw = q[3];
    const u64 xx = f2mul(qx, qx), yy = f2mul(qy, qy), zz = f2mul(qz, qz);
    const u64 xy = f2mul(qx, qy), xz = f2mul(qx, qz), yz = f2mul(qy, qz);
    const u64 xw = f2mul(qx, qw), yw = f2mul(qy, qw), zw = f2mul(qz, qw);

    const u64 r00 = f2fma(n2, f2add(yy, zz), one);
    const u64 r01 = f2mul(two, SUBP(xy, zw));
    const u64 r02 = f2mul(two, f2add(xz, yw));
    const u64 r10 = f2mul(two, f2add(xy, zw));
    const u64 r11 = f2fma(n2, f2add(xx, zz), one);
    const u64 r12 = f2mul(two, SUBP(yz, xw));
    const u64 r20 = f2mul(two, SUBP(xz, yw));
    const u64 r21 = f2mul(two, f2add(yz, xw));
    const u64 r22 = f2fma(n2, f2add(xx, yy), one);

    const u64 v0 = v[0], v1 = v[1], v2 = v[2];
    const u64 w0 = v[3], w1 = v[4], w2 = v[5];

    pd[0] = f2fma(r02, v2, f2fma(r01, v1, f2mul(r00, v0)));
    pd[1] = f2fma(r12, v2, f2fma(r11, v1, f2mul(r10, v0)));
    pd[2] = f2fma(r22, v2, f2fma(r21, v1, f2mul(r20, v0)));
    // pd3 = -0.5*(qx w0 + qy w1 + qz w2)
    pd[3] = f2mul(nhalf, f2fma(qz, w2, f2fma(qy, w1, f2mul(qx, w0))));
    // pd4 = 0.5*(qw w0 - qz w1 + qy w2)
    pd[4] = f2mul(half, f2fma(qy, w2, SUBP(f2mul(qw, w0), f2mul(qz, w1))));
    // pd5 = 0.5*(qz w0 + qw w1 - qx w2)
    pd[5] = f2mul(half, SUBP(f2fma(qw, w1, f2mul(qz, w0)), f2mul(qx, w2)));
    // pd6 = 0.5*(-qy w0 + qx w1 + qw w2)
    pd[6] = f2mul(half, f2fma(qw, w2, SUBP(f2mul(qx, w1), f2mul(qy, w0))));

    // mv = mTot @ v
    u64 mv[6];
#pragma unroll
    for (int i = 0; i < 6; i++) mv[i] = f2mul(CD(CMTOT, 0 * 6 + i), v0);
#pragma unroll
    for (int j = 1; j < 6; j++)
#pragma unroll
        for (int i = 0; i < 6; i++) mv[i] = f2fma(CD(CMTOT, j * 6 + i), v[j], mv[i]);

    // s = quad|v|v - Cv
    u64 s[6];
#pragma unroll
    for (int i = 0; i < 6; i++)
        s[i] = f2mul(CD(CQD, i), f2mul(f2abs(v[i]), v[i]));
    s[0] = f2fma(mv[1], w2, s[0]);  s[0] = SUBP(s[0], f2mul(mv[2], w1));
    s[1] = f2fma(mv[2], w0, s[1]);  s[1] = SUBP(s[1], f2mul(mv[0], w2));
    s[2] = f2fma(mv[0], w1, s[2]);  s[2] = SUBP(s[2], f2mul(mv[1], w0));
    s[3] = f2fma(mv[1], v2, s[3]);  s[3] = SUBP(s[3], f2mul(mv[2], v1));
    s[3] = f2fma(mv[4], w2, s[3]);  s[3] = SUBP(s[3], f2mul(mv[5], w1));
    s[4] = f2fma(mv[2], v0, s[4]);  s[4] = SUBP(s[4], f2mul(mv[0], v2));
    s[4] = f2fma(mv[5], w0, s[4]);  s[4] = SUBP(s[4], f2mul(mv[3], w2));
    s[5] = f2fma(mv[0], v1, s[5]);  s[5] = SUBP(s[5], f2mul(mv[1], v0));
    s[5] = f2fma(mv[3], w1, s[5]);  s[5] = SUBP(s[5], f2mul(mv[4], w0));

    // optional linDampFow: s_i += v_i * (lf_i . v)
    if (c_consts[CFLAG] != 0.0f) {
        u64 d[6];
#pragma unroll
        for (int i = 0; i < 6; i++) d[i] = f2mul(CD(CLF, 0 * 6 + i), v0);
#pragma unroll
        for (int j = 1; j < 6; j++)
#pragma unroll
            for (int i = 0; i < 6; i++) d[i] = f2fma(CD(CLF, j * 6 + i), v[j], d[i]);
#pragma unroll
        for (int i = 0; i < 6; i++) s[i] = f2fma(v[i], d[i], s[i]);
    }

    // vd = Uv + MiLD@v + Minv@s + negGm@r2
    u64 a[6];
#pragma unroll
    for (int i = 0; i < 6; i++) a[i] = Uv[i];
#pragma unroll
    for (int j = 0; j < 6; j++)
#pragma unroll
        for (int i = 0; i < 6; i++) a[i] = f2fma(CD(CMILD, j * 6 + i), v[j], a[i]);
#pragma unroll
    for (int j = 0; j < 6; j++)
#pragma unroll
        for (int i = 0; i < 6; i++) a[i] = f2fma(CD(CMINV, j * 6 + i), s[j], a[i]);
    const u64 rr[3] = { r20, r21, r22 };
#pragma unroll
    for (int jj = 0; jj < 3; jj++)
#pragma unroll
        for (int i = 0; i < 6; i++) a[i] = f2fma(CD(CNEGGM, jj * 6 + i), rr[jj], a[i]);
#pragma unroll
    for (int i = 0; i < 6; i++) vd[i] = a[i];
#undef SUBP
}

// 128 threads, lanes = rows: thread owns rows tid (lo lane) and tid+128 (hi).
__global__ __launch_bounds__(128) void auv_kernel(const float* __restrict__ x,
                                                  const float* __restrict__ u,
                                                  float* __restrict__ out, int K) {
    __shared__ float sx[256 * 13];
    __shared__ float su[256 * 6];

    const int tid = threadIdx.x;
    const int rbase = blockIdx.x * 256;
    const int total_x = K * 13;
    const int total_u = K * 6;
    const int remx = total_x - rbase * 13;
    const int remu = total_u - rbase * 6;

    // Coalesced staging
    if (remx >= 256 * 13 && remu >= 256 * 6) {
        const float4* x4 = (const float4*)(x + (size_t)rbase * 13);
        float4* sx4 = (float4*)sx;
#pragma unroll
        for (int i = tid; i < 256 * 13 / 4; i += 128) sx4[i] = x4[i];
        const float4* u4 = (const float4*)(u + (size_t)rbase * 6);
        float4* su4 = (float4*)su;
#pragma unroll
        for (int i = tid; i < 256 * 6 / 4; i += 128) su4[i] = u4[i];
    } else {
        for (int i = tid; i < 256 * 13; i += 128)
            sx[i] = (i < remx) ? x[rbase * 13 + i] : 0.0f;
        for (int i = tid; i < 256 * 6; i += 128)
            su[i] = (i < remu) ? u[rbase * 6 + i] : 0.0f;
    }
    __syncthreads();

    float* mxA = &sx[tid * 13];
    float* mxB = &sx[(tid + 128) * 13];
    const float* suA = &su[tid * 6];
    const float* suB = &su[(tid + 128) * 6];

    // Lane-paired state
    u64 q[4], v[6];
#pragma unroll
    for (int i = 0; i < 4; i++) q[i] = pk2(mxA[3 + i], mxB[3 + i]);
#pragma unroll
    for (int i = 0; i < 6; i++) v[i] = pk2(mxA[7 + i], mxB[7 + i]);

    // Uv = Minv @ u (lane-paired)
    u64 Uv[6];
    {
        u64 up0 = pk2(suA[0], suB[0]);
#pragma unroll
        for (int i = 0; i < 6; i++) Uv[i] = f2mul(CD(CMINV, 0 * 6 + i), up0);
#pragma unroll
        for (int j = 1; j < 6; j++) {
            const u64 upj = pk2(suA[j], suB[j]);
#pragma unroll
            for (int i = 0; i < 6; i++) Uv[i] = f2fma(CD(CMINV, j * 6 + i), upj, Uv[i]);
        }
    }

    // Stage 1
    u64 pd1[7], vd1[6];
    stage_pair(q, v, Uv, pd1, vd1);

    // Midpoint
    const u64 dt = splat2(KDT);
    u64 q2[4], v2[6];
#pragma unroll
    for (int i = 0; i < 4; i++) q2[i] = f2fma(dt, pd1[3 + i], q[i]);
#pragma unroll
    for (int i = 0; i < 6; i++) v2[i] = f2fma(dt, vd1[i], v[i]);

    // Stage 2
    u64 pd2[7], vd2[6];
    stage_pair(q2, v2, Uv, pd2, vd2);

    // Combine + quaternion normalize (orig pos/q/v reloaded from intact smem)
    const u64 hdt = splat2(0.5f * KDT);
    float rA, rB;
#pragma unroll
    for (int i = 0; i < 3; i++) {
        u64 p0 = pk2(mxA[i], mxB[i]);
        u64 rp = f2fma(hdt, f2add(pd1[i], pd2[i]), p0);
        unpk2(rp, rA, rB); mxA[i] = rA; mxB[i] = rB;
    }
    u64 qo[4];
#pragma unroll
    for (int i = 0; i < 4; i++) {
        u64 q0 = pk2(mxA[3 + i], mxB[3 + i]);
        qo[i] = f2fma(hdt, f2add(pd1[3 + i], pd2[3 + i]), q0);
    }
    u64 nn = f2mul(qo[0], qo[0]);
    nn = f2fma(qo[1], qo[1], nn);
    nn = f2fma(qo[2], qo[2], nn);
    nn = f2fma(qo[3], qo[3], nn);
    float nA, nB; unpk2(nn, nA, nB);
    const u64 ns = pk2(rsqrtf(nA), rsqrtf(nB));
#pragma unroll
    for (int i = 0; i < 4; i++) {
        u64 rp = f2mul(qo[i], ns);
        unpk2(rp, rA, rB); mxA[3 + i] = rA; mxB[3 + i] = rB;
    }
#pragma unroll
    for (int i = 0; i < 6; i++) {
        u64 v0 = pk2(mxA[7 + i], mxB[7 + i]);
        u64 rp = f2fma(hdt, f2add(vd1[i], vd2[i]), v0);
        unpk2(rp, rA, rB); mxA[7 + i] = rA; mxB[7 + i] = rB;
    }
    __syncthreads();

    // Coalesced writeback (bounds-checked; garbage in tail rows never stored)
    if (remx >= 256 * 13) {
        float4* o4 = (float4*)(out + (size_t)rbase * 13);
        const float4* sx4 = (const float4*)sx;
#pragma unroll
        for (int i = tid; i < 256 * 13 / 4; i += 128) o4[i] = sx4[i];
    } else {
        for (int i = tid; i < 256 * 13; i += 128)
            if (i < remx) out[rbase * 13 + i] = sx[i];
    }
}

extern "C" void kernel_launch(void* const* d_in, const int* in_sizes, int n_in,
                              void* d_out, int out_size) {
    const float* x          = (const float*)d_in[0];
    const float* u          = (const float*)d_in[1];
    const float* mass       = (const float*)d_in[2];
    const float* volume     = (const float*)d_in[3];
    const float* cog        = (const float*)d_in[4];
    const float* cob        = (const float*)d_in[5];
    const float* mTot       = (const float*)d_in[6];
    const float* linDamp    = (const float*)d_in[7];
    const float* linDampFow = (const float*)d_in[8];
    const float* quadDamp   = (const float*)d_in[9];

    const int K = in_sizes[0] / 13;

    void* csym = nullptr;
    cudaGetSymbolAddress(&csym, c_consts);

    prep_kernel<<<1, 64>>>((float*)csym, mass, volume, cog, cob,
                           mTot, linDamp, linDampFow, quadDamp);

    const int blocks = (K + 255) / 256;
    auv_kernel<<<blocks, 128>>>(x, u, (float*)d_out, K);
}